// round 12
// baseline (speedup 1.0000x reference)
#include <cuda_runtime.h>

typedef unsigned long long ull;
typedef unsigned char u8;

#define Nn 64
#define C1 512
#define C2 128
#define C3 32
#define HW 784
#define NPIX (Nn*HW)   // 50176

#define FMAXV 3.402823466e38f

// ---------------- device scratch ----------------
__device__ float g_a1[C1], g_b1v[C1], g_a2[C2], g_b2v[C2];
__device__ uint4 g_w1p[8*16*32];                // w1 u8 codes, mma-fragment-permuted
__device__ float g_j1row[C2];                   // per-co sum of w1 codes
__device__ uint4 g_w2p[2304];                   // w2 codes fragment-packed
__device__ float g_Jtap[C3*9];                  // per-(co,tap) code sums
__device__ float g_Jall[C3];                    // per-co total code sums
__device__ __align__(16) float g_h2buf[NPIX*C2];   // h2 pre-quant, [pixel][co] layout
__device__ __align__(16) u8    g_h2q[NPIX*C2];     // h2 u8 codes, [pixel][ci] layout
__device__ float g_T[NPIX];                        // per-pixel sum of codes
__device__ unsigned g_h1mn, g_h1mx, g_h2mn, g_h2mx;  // nonneg floats as uint bits
__device__ unsigned g_wmm[4];                   // monotone-mapped {w1mn,w1mx,w2mn,w2mx}
__device__ unsigned g_xmn[C1], g_xmx[C1];       // per-channel raw x min/max (monotone-mapped)

// ---------------- helpers ----------------
__device__ __forceinline__ void mma_u8(int* d, unsigned a0, unsigned a1, unsigned a2, unsigned a3,
                                       unsigned b0, unsigned b1) {
    asm volatile("mma.sync.aligned.m16n8k32.row.col.s32.u8.u8.s32 "
                 "{%0,%1,%2,%3},{%4,%5,%6,%7},{%8,%9},{%0,%1,%2,%3};"
                 : "+r"(d[0]), "+r"(d[1]), "+r"(d[2]), "+r"(d[3])
                 : "r"(a0), "r"(a1), "r"(a2), "r"(a3), "r"(b0), "r"(b1));
}
__device__ __forceinline__ float wredmin(float v) {
    #pragma unroll
    for (int o = 16; o > 0; o >>= 1) v = fminf(v, __shfl_xor_sync(0xffffffffu, v, o));
    return v;
}
__device__ __forceinline__ float wredmax(float v) {
    #pragma unroll
    for (int o = 16; o > 0; o >>= 1) v = fmaxf(v, __shfl_xor_sync(0xffffffffu, v, o));
    return v;
}
__device__ __forceinline__ float wredsum(float v) {
    #pragma unroll
    for (int o = 16; o > 0; o >>= 1) v += __shfl_xor_sync(0xffffffffu, v, o);
    return v;
}
// order-preserving float<->unsigned map (handles negatives)
__device__ __forceinline__ unsigned fmap(float f) {
    unsigned u = __float_as_uint(f);
    return (u & 0x80000000u) ? ~u : (u | 0x80000000u);
}
__device__ __forceinline__ float funmap(unsigned m) {
    return __uint_as_float((m & 0x80000000u) ? (m ^ 0x80000000u) : ~m);
}

// ---------------- 1: prep ----------------
__global__ void prep_k(const float* __restrict__ g1, const float* __restrict__ b1,
                       const float* __restrict__ m1, const float* __restrict__ v1,
                       const float* __restrict__ g2, const float* __restrict__ b2,
                       const float* __restrict__ m2, const float* __restrict__ v2) {
    int t = threadIdx.x;
    if (t == 0) {
        g_h1mn = 0x7f7fffffu; g_h1mx = 0u; g_h2mn = 0x7f7fffffu; g_h2mx = 0u;
        g_wmm[0] = 0xFFFFFFFFu; g_wmm[1] = 0u; g_wmm[2] = 0xFFFFFFFFu; g_wmm[3] = 0u;
    }
    if (t < C1) {
        float inv = g1[t] / sqrtf(v1[t] + 1e-5f);
        g_a1[t] = inv; g_b1v[t] = b1[t] - m1[t] * inv;
        g_xmn[t] = 0xFFFFFFFFu; g_xmx[t] = 0u;
    }
    if (t < C2) {
        float inv = g2[t] / sqrtf(v2[t] + 1e-5f);
        g_a2[t] = inv; g_b2v[t] = b2[t] - m2[t] * inv;
    }
}

// ---------------- 2a: weight min/max (parallel, atomics) ----------------
// blocks 0..15: w1 (16 x 4096 = 65536); blocks 16..23: w2 (8 x 4608 = 36864)
__global__ void wmm_k(const float* __restrict__ w1, const float* __restrict__ w2) {
    __shared__ float smn[8], smx[8];
    const int b = blockIdx.x, t = threadIdx.x;
    const float* w; int cnt, slot;
    if (b < 16) { w = w1 + b * 4096; cnt = 4096; slot = 0; }
    else        { w = w2 + (b - 16) * 4608; cnt = 4608; slot = 2; }
    float mn = FMAXV, mx = -FMAXV;
    for (int i = t; i < cnt; i += 256) { float v = w[i]; mn = fminf(mn, v); mx = fmaxf(mx, v); }
    float bm = wredmin(mn), bM = wredmax(mx);
    int wd = t >> 5, ln = t & 31;
    if (ln == 0) { smn[wd] = bm; smx[wd] = bM; }
    __syncthreads();
    if (wd == 0) {
        float m2 = (ln < 8) ? smn[ln] : FMAXV;
        float M2 = (ln < 8) ? smx[ln] : -FMAXV;
        m2 = wredmin(m2); M2 = wredmax(M2);
        if (ln == 0) {
            atomicMin(&g_wmm[slot], fmap(m2));
            atomicMax(&g_wmm[slot + 1], fmap(M2));
        }
    }
}

// ---------------- 2b: weight pack (parallel) ----------------
__global__ void wpack_k(const float* __restrict__ w1, const float* __restrict__ w2) {
    const int b = blockIdx.x, t = threadIdx.x;
    if (b < 16) {
        const float mnv = funmap(g_wmm[0]);
        const float sc = fmaxf((funmap(g_wmm[1]) - mnv) * (1.f / 255.f), 1e-8f);
        {
            int f = b * 256 + t;
            int m = f >> 9;
            int rem = f & 511;
            int q = rem >> 5, L = rem & 31;
            unsigned rg[4];
            #pragma unroll
            for (int r = 0; r < 4; r++) {
                int row = m * 16 + (L >> 2) + (r & 1) * 8;
                int kc = q * 32 + (r >> 1) * 16 + (L & 3) * 4;
                unsigned u = 0;
                #pragma unroll
                for (int i = 0; i < 4; i++) {
                    int code = __float2int_rn(__fdiv_rn(w1[row * C1 + kc + i] - mnv, sc));
                    u |= ((unsigned)code & 0xffu) << (8 * i);
                }
                rg[r] = u;
            }
            g_w1p[f] = make_uint4(rg[0], rg[1], rg[2], rg[3]);
        }
        {
            int wd = t >> 5, ln = t & 31;
            int co = b * 8 + wd;
            float s = 0.f;
            #pragma unroll
            for (int i = 0; i < 16; i++)
                s += (float)__float2int_rn(__fdiv_rn(w1[co * C1 + i * 32 + ln] - mnv, sc));
            s = wredsum(s);
            if (ln == 0) g_j1row[co] = s;
        }
    } else {
        __shared__ u8 s_code[C3 * C2 * 9];
        const float mnv = funmap(g_wmm[2]);
        const float sc = fmaxf((funmap(g_wmm[3]) - mnv) * (1.f / 255.f), 1e-8f);
        for (int i = t; i < C3 * C2 * 9; i += 256)
            s_code[i] = (u8)__float2int_rn(__fdiv_rn(w2[i] - mnv, sc));
        __syncthreads();
        for (int e = t; e < C3 * 9; e += 256) {
            int co = e / 9, tap = e - co * 9;
            int s = 0;
            for (int ci = 0; ci < C2; ci++) s += s_code[(co * C2 + ci) * 9 + tap];
            g_Jtap[e] = (float)s;
        }
        if (t < C3) {
            int s = 0;
            for (int i = 0; i < C2 * 9; i++) s += s_code[t * C2 * 9 + i];
            g_Jall[t] = (float)s;
        }
        for (int f = t; f < 2304; f += 256) {
            int lane = f & 31;
            int u = f >> 5;
            int mtile = u & 1;
            int v2i = u >> 1;
            int g = v2i & 3, tap = v2i >> 2;
            int co_b = mtile * 16 + (lane >> 2);
            int ci_b = g * 32 + (lane & 3) * 4;
            unsigned rg[4];
            #pragma unroll
            for (int r = 0; r < 4; r++) {
                int co = co_b + (r & 1) * 8;
                int ci0 = ci_b + (r >> 1) * 16;
                unsigned uu = 0;
                #pragma unroll
                for (int i = 0; i < 4; i++)
                    uu |= ((unsigned)s_code[(co * C2 + ci0 + i) * 9 + tap]) << (8 * i);
                rg[r] = uu;
            }
            g_w2p[f] = make_uint4(rg[0], rg[1], rg[2], rg[3]);
        }
    }
}

// ---------------- 3a: per-channel raw min/max of x (warp per plane) ----------------
__global__ __launch_bounds__(256) void h1mm_k(const float* __restrict__ x) {
    const int b = blockIdx.x, t = threadIdx.x;
    const int w = t >> 5, ln = t & 31;
    #pragma unroll
    for (int sub = 0; sub < 2; sub++) {
        const int plane = b * 16 + w * 2 + sub;      // 0..32767
        const int ci = plane & 511;
        const float4* p = (const float4*)x + plane * 196;
        float mn = FMAXV, mx = -FMAXV;
        #pragma unroll 4
        for (int i = ln; i < 196; i += 32) {
            float4 v = p[i];
            mn = fminf(mn, fminf(fminf(v.x, v.y), fminf(v.z, v.w)));
            mx = fmaxf(mx, fmaxf(fmaxf(v.x, v.y), fmaxf(v.z, v.w)));
        }
        mn = wredmin(mn); mx = wredmax(mx);
        if (ln == 0) {
            atomicMin(&g_xmn[ci], fmap(mn));
            atomicMax(&g_xmx[ci], fmap(mx));
        }
    }
}

// ---------------- 3b: fold channel extremes through relu(BN1) (monotone) ----------------
__global__ void mm2_k() {
    __shared__ float smn[16], smx[16];
    const int t = threadIdx.x, w = t >> 5, ln = t & 31;
    float a = g_a1[t], bb = g_b1v[t];
    float rmn = funmap(g_xmn[t]), rmx = funmap(g_xmx[t]);
    float lo = fmaxf(fmaf(a, (a >= 0.f) ? rmn : rmx, bb), 0.f);
    float hi = fmaxf(fmaf(a, (a >= 0.f) ? rmx : rmn, bb), 0.f);
    lo = wredmin(lo); hi = wredmax(hi);
    if (ln == 0) { smn[w] = lo; smx[w] = hi; }
    __syncthreads();
    if (w == 0) {
        float m2 = (ln < 16) ? smn[ln] : FMAXV;
        float M2 = (ln < 16) ? smx[ln] : 0.f;
        m2 = wredmin(m2); M2 = wredmax(M2);
        if (ln == 0) { g_h1mn = __float_as_uint(m2); g_h1mx = __float_as_uint(M2); }
    }
}

// ---------------- 4: conv1x1 via u8 IMMA, k32 chunks, 4 CTAs/SM ----------------
#define BP1 48
#define BUF1 (64*BP1)   // 3072 B
__global__ __launch_bounds__(256, 4) void conv1_k(const float* __restrict__ x) {
    __shared__ __align__(16) u8 Bs[2 * BUF1];
    __shared__ int kcp[4][64];
    __shared__ float kcolF[64];
    __shared__ float sa1[C1], sb1[C1];
    __shared__ float smn[8], smx[8];

    const int tid = threadIdx.x;
    const int lane = tid & 31, wid = tid >> 5;
    const int col0 = blockIdx.x * 64;

    #pragma unroll
    for (int l = 0; l < 2; l++) {
        int e = tid + l * 256;
        sa1[e] = g_a1[e]; sb1[e] = g_b1v[e];
    }

    const float mn1 = __uint_as_float(g_h1mn);
    const float mx1 = __uint_as_float(g_h1mx);
    const float s1 = fmaxf((mx1 - mn1) * (1.f / 255.f), 1e-8f);
    const float i1 = 1.f / s1;

    const int pB = tid & 63;
    const int tq = tid >> 6;        // ci-octet within chunk
    const int gpB = col0 + pB;
    const int nimgB = gpB / 784;
    const float* xb = x + nimgB * C1 * HW + (gpB - nimgB * 784) + tq * 8 * HW;

    int acc[8][4];
    #pragma unroll
    for (int t = 0; t < 8; t++)
        #pragma unroll
        for (int r = 0; r < 4; r++) acc[t][r] = 0;

    float v[8];
    int ksum = 0;
    #pragma unroll
    for (int j = 0; j < 8; j++) v[j] = xb[j * HW];
    __syncthreads();   // sa1/sb1 ready

    // produce chunk 0
    {
        const int cib = tq * 8;
        #pragma unroll
        for (int s = 0; s < 2; s++) {
            unsigned u = 0;
            #pragma unroll
            for (int j = 0; j < 4; j++) {
                int ci = cib + s * 4 + j;
                float h = fmaxf(fmaf(sa1[ci], v[s * 4 + j], sb1[ci]), 0.f);
                int code = __float2int_rn((h - mn1) * i1);
                ksum += code;
                u |= ((unsigned)code & 0xffu) << (8 * j);
            }
            *(unsigned*)(Bs + pB * BP1 + tq * 8 + s * 4) = u;
        }
    }
    // prefetch chunk 1
    #pragma unroll
    for (int j = 0; j < 8; j++) v[j] = xb[(32 + j) * HW];
    __syncthreads();

    for (int c = 0; c < 16; c++) {
        const u8* curB = Bs + (c & 1) * BUF1;
        if (c < 15) {
            u8* nxtB = Bs + ((c + 1) & 1) * BUF1;
            const int cib = (c + 1) * 32 + tq * 8;
            #pragma unroll
            for (int s = 0; s < 2; s++) {
                unsigned u = 0;
                #pragma unroll
                for (int j = 0; j < 4; j++) {
                    int ci = cib + s * 4 + j;
                    float h = fmaxf(fmaf(sa1[ci], v[s * 4 + j], sb1[ci]), 0.f);
                    int code = __float2int_rn((h - mn1) * i1);
                    ksum += code;
                    u |= ((unsigned)code & 0xffu) << (8 * j);
                }
                *(unsigned*)(nxtB + pB * BP1 + tq * 8 + s * 4) = u;
            }
            if (c < 14) {
                #pragma unroll
                for (int j = 0; j < 8; j++) v[j] = xb[((c + 2) * 32 + j) * HW];
            }
        }
        {
            uint4 a = g_w1p[(wid * 16 + c) * 32 + lane];
            const u8* bbase = curB + (lane >> 2) * BP1 + (lane & 3) * 4;
            #pragma unroll
            for (int t = 0; t < 8; t++) {
                unsigned b0 = *(const unsigned*)(bbase + t * 8 * BP1);
                unsigned b1 = *(const unsigned*)(bbase + t * 8 * BP1 + 16);
                mma_u8(acc[t], a.x, a.y, a.z, a.w, b0, b1);
            }
        }
        __syncthreads();
    }

    kcp[tq][pB] = ksum;
    __syncthreads();
    if (tid < 64) kcolF[tid] = (float)(kcp[0][tid] + kcp[1][tid] + kcp[2][tid] + kcp[3][tid]);
    __syncthreads();

    const float mnv = funmap(g_wmm[0]);
    const float sw = fmaxf((funmap(g_wmm[1]) - mnv) * (1.f / 255.f), 1e-8f);
    const float cS = sw * s1;
    const float cK = mnv * s1;
    const float cJ = sw * mn1;
    const float cD = 512.f * mnv * mn1;

    const int g = lane >> 2;
    const int co0 = wid * 16 + g, co1 = co0 + 8;
    const float base0 = fmaf(cJ, g_j1row[co0], cD);
    const float base1 = fmaf(cJ, g_j1row[co1], cD);
    const float a20 = g_a2[co0], b20 = g_b2v[co0];
    const float a21 = g_a2[co1], b21 = g_b2v[co1];

    float lmn = FMAXV, lmx = 0.f;
    #pragma unroll
    for (int t = 0; t < 8; t++) {
        int pl = t * 8 + (lane & 3) * 2;
        float kc0 = kcolF[pl], kc1 = kcolF[pl + 1];
        float y00 = fmaf(cS, __int2float_rn(acc[t][0]), fmaf(cK, kc0, base0));
        float y01 = fmaf(cS, __int2float_rn(acc[t][1]), fmaf(cK, kc1, base0));
        float y10 = fmaf(cS, __int2float_rn(acc[t][2]), fmaf(cK, kc0, base1));
        float y11 = fmaf(cS, __int2float_rn(acc[t][3]), fmaf(cK, kc1, base1));
        float h00 = fmaxf(fmaf(a20, y00, b20), 0.f);
        float h01 = fmaxf(fmaf(a20, y01, b20), 0.f);
        float h10 = fmaxf(fmaf(a21, y10, b21), 0.f);
        float h11 = fmaxf(fmaf(a21, y11, b21), 0.f);
        lmn = fminf(lmn, fminf(fminf(h00, h01), fminf(h10, h11)));
        lmx = fmaxf(lmx, fmaxf(fmaxf(h00, h01), fmaxf(h10, h11)));
        int px0 = col0 + pl;
        g_h2buf[px0 * C2 + co0]       = h00;
        g_h2buf[(px0 + 1) * C2 + co0] = h01;
        g_h2buf[px0 * C2 + co1]       = h10;
        g_h2buf[(px0 + 1) * C2 + co1] = h11;
    }
    float bm = wredmin(lmn), bM = wredmax(lmx);
    if (lane == 0) { smn[wid] = bm; smx[wid] = bM; }
    __syncthreads();
    if (wid == 0) {
        float m2 = (lane < 8) ? smn[lane] : FMAXV;
        float M2 = (lane < 8) ? smx[lane] : 0.f;
        m2 = wredmin(m2); M2 = wredmax(M2);
        if (lane == 0) {
            atomicMin(&g_h2mn, __float_as_uint(m2));
            atomicMax(&g_h2mx, __float_as_uint(M2));
        }
    }
}

// ---------------- 4.5: h2 -> u8 codes (8 threads/pixel, coalesced) ----------------
__global__ __launch_bounds__(256) void codes_k() {
    const int t = blockIdx.x * 256 + threadIdx.x;
    const int gp = t >> 3;
    const int sub = t & 7;
    const float mn = __uint_as_float(g_h2mn);
    const float mx = __uint_as_float(g_h2mx);
    const float s = fmaxf((mx - mn) * (1.f / 255.f), 1e-8f);
    const float inv = 1.f / s;
    const float4* src = (const float4*)(g_h2buf + (size_t)gp * C2) + sub * 4;
    int ksum = 0;
    unsigned wds[4];
    #pragma unroll
    for (int j = 0; j < 4; j++) {
        float4 v = src[j];
        int c0 = __float2int_rn((v.x - mn) * inv);
        int c1 = __float2int_rn((v.y - mn) * inv);
        int c2 = __float2int_rn((v.z - mn) * inv);
        int c3 = __float2int_rn((v.w - mn) * inv);
        ksum += c0 + c1 + c2 + c3;
        wds[j] = (unsigned)c0 | ((unsigned)c1 << 8) | ((unsigned)c2 << 16) | ((unsigned)c3 << 24);
    }
    ((uint4*)(g_h2q + (size_t)gp * C2))[sub] = make_uint4(wds[0], wds[1], wds[2], wds[3]);
    ksum += __shfl_down_sync(0xffffffffu, ksum, 4, 8);
    ksum += __shfl_down_sync(0xffffffffu, ksum, 2, 8);
    ksum += __shfl_down_sync(0xffffffffu, ksum, 1, 8);
    if (sub == 0) g_T[gp] = (float)ksum;
}

// ---------------- 5: conv3x3 via u8 IMMA, 2 images per block ----------------
#define BP2 144
__global__ __launch_bounds__(224) void conv2_k(float* __restrict__ out) {
    __shared__ uint4 s_w[2304];                       // 36864 B
    __shared__ __align__(16) u8 s_b[2][4 * 30 * BP2]; // 2 x 17280 B
    __shared__ float s_T[2][112];
    __shared__ float s_K9[2][56];
    __shared__ float s_Jtap[C3 * 9];
    __shared__ float s_Jall[C3];

    const int tid = threadIdx.x;
    const int lane = tid & 31, wid = tid >> 5;
    const int n0 = blockIdx.y * 2, sl = blockIdx.x;
    const int r0 = sl * 2;

    for (int f = tid; f < 2304; f += 224) s_w[f] = g_w2p[f];
    // stage codes for both images (zero-padded halo)
    for (int idx = tid; idx < 1920; idx += 224) {
        int im = idx / 960;
        int rem = idx - im * 960;
        int j = rem & 7;
        int slot = rem >> 3;
        int cc = slot % 30, l = slot / 30;
        int gr = r0 - 1 + l, gc = cc - 1;
        uint4 vv = make_uint4(0u, 0u, 0u, 0u);
        if ((unsigned)gr < 28u && (unsigned)gc < 28u)
            vv = *(const uint4*)(g_h2q + ((size_t)((n0 + im) * 784 + gr * 28 + gc)) * C2 + j * 16);
        *(uint4*)(s_b[im] + (size_t)slot * BP2 + j * 16) = vv;
    }
    if (tid < 224) {
        int im = tid / 112, e = tid - im * 112;
        int rr = r0 - 1 + e / 28, cc = e - (e / 28) * 28;
        s_T[im][e] = ((unsigned)rr < 28u) ? g_T[(n0 + im) * 784 + rr * 28 + cc] : 0.f;
    }
    for (int e = tid; e < C3 * 9; e += 224) s_Jtap[e] = g_Jtap[e];
    if (tid < C3) s_Jall[tid] = g_Jall[tid];
    __syncthreads();
    if (tid < 112) {
        int im = tid / 56, q = tid - im * 56;
        int rl2 = q / 28, c = q - rl2 * 28;
        float s = 0.f;
        #pragma unroll
        for (int dr = 0; dr < 3; dr++) {
            #pragma unroll
            for (int dc = -1; dc <= 1; dc++) {
                int cc = c + dc;
                if ((unsigned)cc < 28u) s += s_T[im][(rl2 + dr) * 28 + cc];
            }
        }
        s_K9[im][q] = s;
    }
    __syncthreads();

    const int ql = wid * 8 + (lane >> 2);
    const int rl = ql / 28, cl = ql - (ql / 28) * 28;

    int acc[2][2][4];
    #pragma unroll
    for (int im = 0; im < 2; im++)
        #pragma unroll
        for (int h = 0; h < 2; h++)
            #pragma unroll
            for (int r = 0; r < 4; r++) acc[im][h][r] = 0;

    #pragma unroll
    for (int im = 0; im < 2; im++) {
        #pragma unroll
        for (int t = 0; t < 9; t++) {
            const int dr = t / 3, dc = t % 3;
            const u8* bt = s_b[im] + (size_t)((rl + dr) * 30 + (cl + dc)) * BP2 + (lane & 3) * 4;
            #pragma unroll
            for (int g = 0; g < 4; g++) {
                unsigned b0 = *(const unsigned*)(bt + g * 32);
                unsigned b1 = *(const unsigned*)(bt + g * 32 + 16);
                uint4 a0 = s_w[((t * 4 + g) * 2 + 0) * 32 + lane];
                mma_u8(acc[im][0], a0.x, a0.y, a0.z, a0.w, b0, b1);
                uint4 a1 = s_w[((t * 4 + g) * 2 + 1) * 32 + lane];
                mma_u8(acc[im][1], a1.x, a1.y, a1.z, a1.w, b0, b1);
            }
        }
    }

    const float mn2 = __uint_as_float(g_h2mn);
    const float mx2 = __uint_as_float(g_h2mx);
    const float s2 = fmaxf((mx2 - mn2) * (1.f / 255.f), 1e-8f);
    const float mnv = funmap(g_wmm[2]);
    const float sw = fmaxf((funmap(g_wmm[3]) - mnv) * (1.f / 255.f), 1e-8f);
    const float cS = sw * s2;
    const float cK = mnv * s2;
    const float cJ = sw * mn2;
    const float cD = 1152.f * mnv * mn2;

    const int qa = wid * 8 + 2 * (lane & 3);
    const int co_r = lane >> 2;

    #pragma unroll
    for (int im = 0; im < 2; im++) {
        #pragma unroll
        for (int e = 0; e < 2; e++) {
            const int q = qa + e;
            const float k9 = s_K9[im][q];
            const int r = r0 + q / 28, c = q - (q / 28) * 28;
            const bool border = (r == 0) | (r == 27) | (c == 0) | (c == 27);
            int npad = 0;
            float sj[4] = {0.f, 0.f, 0.f, 0.f};
            if (border) {
                #pragma unroll
                for (int t = 0; t < 9; t++) {
                    const int dr = t / 3 - 1, dc = t % 3 - 1;
                    const bool pad = ((unsigned)(r + dr) >= 28u) || ((unsigned)(c + dc) >= 28u);
                    if (pad) {
                        npad++;
                        #pragma unroll
                        for (int m = 0; m < 4; m++) sj[m] += s_Jtap[(co_r + 8 * m) * 9 + t];
                    }
                }
            }
            #pragma unroll
            for (int m = 0; m < 4; m++) {
                const int co = co_r + 8 * m;
                int S = (m < 2) ? acc[im][0][2 * m + e] : acc[im][1][2 * (m - 2) + e];
                float y = fmaf(cS, __int2float_rn(S), fmaf(cK, k9, fmaf(cJ, s_Jall[co], cD)));
                if (border) y -= mn2 * fmaf(sw, sj[m], mnv * 128.f * (float)npad);
                out[((n0 + im) * C3 + co) * HW + r * 28 + c] = y;
            }
        }
    }
}

// ---------------- launch ----------------
extern "C" void kernel_launch(void* const* d_in, const int* in_sizes, int n_in,
                              void* d_out, int out_size) {
    const float* x  = (const float*)d_in[0];
    const float* g1 = (const float*)d_in[1];
    const float* b1 = (const float*)d_in[2];
    const float* m1 = (const float*)d_in[3];
    const float* v1 = (const float*)d_in[4];
    const float* w1 = (const float*)d_in[5];
    const float* g2 = (const float*)d_in[6];
    const float* b2 = (const float*)d_in[7];
    const float* m2 = (const float*)d_in[8];
    const float* v2 = (const float*)d_in[9];
    const float* w2 = (const float*)d_in[10];
    float* out = (float*)d_out;

    prep_k<<<1, 512>>>(g1, b1, m1, v1, g2, b2, m2, v2);
    wmm_k<<<24, 256>>>(w1, w2);
    wpack_k<<<17, 256>>>(w1, w2);
    h1mm_k<<<2048, 256>>>(x);
    mm2_k<<<1, 512>>>();
    conv1_k<<<NPIX / 64, 256>>>(x);
    codes_k<<<NPIX * 8 / 256, 256>>>();
    conv2_k<<<dim3(14, Nn / 2), 224>>>(out);
}

// round 13
// speedup vs baseline: 1.0231x; 1.0231x over previous
#include <cuda_runtime.h>

typedef unsigned long long ull;
typedef unsigned char u8;

#define Nn 64
#define C1 512
#define C2 128
#define C3 32
#define HW 784
#define NPIX (Nn*HW)   // 50176

#define FMAXV 3.402823466e38f

// ---------------- device scratch ----------------
__device__ float g_a1[C1], g_b1v[C1], g_a2[C2], g_b2v[C2];
__device__ uint4 g_w1p[8*16*32];                // w1 u8 codes, mma-fragment-permuted
__device__ float g_j1row[C2];                   // per-co sum of w1 codes
__device__ uint4 g_w2p[2304];                   // w2 codes fragment-packed
__device__ float g_Jtap[C3*9];                  // per-(co,tap) code sums
__device__ float g_Jall[C3];                    // per-co total code sums
__device__ __align__(16) float g_h2buf[NPIX*C2];   // h2 pre-quant, [pixel][co] layout
__device__ __align__(16) u8    g_h2q[NPIX*C2];     // h2 u8 codes, [pixel][ci] layout
__device__ float g_T[NPIX];                        // per-pixel sum of codes
__device__ unsigned g_h1mn, g_h1mx, g_h2mn, g_h2mx;  // nonneg floats as uint bits
__device__ unsigned g_wmm[4];                   // monotone-mapped {w1mn,w1mx,w2mn,w2mx}
__device__ unsigned g_xmn[C1], g_xmx[C1];       // per-channel raw x min/max (monotone-mapped)

// ---------------- helpers ----------------
__device__ __forceinline__ void mma_u8(int* d, unsigned a0, unsigned a1, unsigned a2, unsigned a3,
                                       unsigned b0, unsigned b1) {
    asm volatile("mma.sync.aligned.m16n8k32.row.col.s32.u8.u8.s32 "
                 "{%0,%1,%2,%3},{%4,%5,%6,%7},{%8,%9},{%0,%1,%2,%3};"
                 : "+r"(d[0]), "+r"(d[1]), "+r"(d[2]), "+r"(d[3])
                 : "r"(a0), "r"(a1), "r"(a2), "r"(a3), "r"(b0), "r"(b1));
}
__device__ __forceinline__ float wredmin(float v) {
    #pragma unroll
    for (int o = 16; o > 0; o >>= 1) v = fminf(v, __shfl_xor_sync(0xffffffffu, v, o));
    return v;
}
__device__ __forceinline__ float wredmax(float v) {
    #pragma unroll
    for (int o = 16; o > 0; o >>= 1) v = fmaxf(v, __shfl_xor_sync(0xffffffffu, v, o));
    return v;
}
__device__ __forceinline__ float wredsum(float v) {
    #pragma unroll
    for (int o = 16; o > 0; o >>= 1) v += __shfl_xor_sync(0xffffffffu, v, o);
    return v;
}
// order-preserving float<->unsigned map (handles negatives)
__device__ __forceinline__ unsigned fmap(float f) {
    unsigned u = __float_as_uint(f);
    return (u & 0x80000000u) ? ~u : (u | 0x80000000u);
}
__device__ __forceinline__ float funmap(unsigned m) {
    return __uint_as_float((m & 0x80000000u) ? (m ^ 0x80000000u) : ~m);
}

// ---------------- 1: prep ----------------
__global__ void prep_k(const float* __restrict__ g1, const float* __restrict__ b1,
                       const float* __restrict__ m1, const float* __restrict__ v1,
                       const float* __restrict__ g2, const float* __restrict__ b2,
                       const float* __restrict__ m2, const float* __restrict__ v2) {
    int t = threadIdx.x;
    if (t == 0) {
        g_h1mn = 0x7f7fffffu; g_h1mx = 0u; g_h2mn = 0x7f7fffffu; g_h2mx = 0u;
        g_wmm[0] = 0xFFFFFFFFu; g_wmm[1] = 0u; g_wmm[2] = 0xFFFFFFFFu; g_wmm[3] = 0u;
    }
    if (t < C1) {
        float inv = g1[t] / sqrtf(v1[t] + 1e-5f);
        g_a1[t] = inv; g_b1v[t] = b1[t] - m1[t] * inv;
        g_xmn[t] = 0xFFFFFFFFu; g_xmx[t] = 0u;
    }
    if (t < C2) {
        float inv = g2[t] / sqrtf(v2[t] + 1e-5f);
        g_a2[t] = inv; g_b2v[t] = b2[t] - m2[t] * inv;
    }
}

// ---------------- 2a: weight min/max (parallel, atomics) ----------------
// blocks 0..15: w1 (16 x 4096 = 65536); blocks 16..23: w2 (8 x 4608 = 36864)
__global__ void wmm_k(const float* __restrict__ w1, const float* __restrict__ w2) {
    __shared__ float smn[8], smx[8];
    const int b = blockIdx.x, t = threadIdx.x;
    const float* w; int cnt, slot;
    if (b < 16) { w = w1 + b * 4096; cnt = 4096; slot = 0; }
    else        { w = w2 + (b - 16) * 4608; cnt = 4608; slot = 2; }
    float mn = FMAXV, mx = -FMAXV;
    for (int i = t; i < cnt; i += 256) { float v = w[i]; mn = fminf(mn, v); mx = fmaxf(mx, v); }
    float bm = wredmin(mn), bM = wredmax(mx);
    int wd = t >> 5, ln = t & 31;
    if (ln == 0) { smn[wd] = bm; smx[wd] = bM; }
    __syncthreads();
    if (wd == 0) {
        float m2 = (ln < 8) ? smn[ln] : FMAXV;
        float M2 = (ln < 8) ? smx[ln] : -FMAXV;
        m2 = wredmin(m2); M2 = wredmax(M2);
        if (ln == 0) {
            atomicMin(&g_wmm[slot], fmap(m2));
            atomicMax(&g_wmm[slot + 1], fmap(M2));
        }
    }
}

// ---------------- 2b: weight pack (parallel) ----------------
__global__ void wpack_k(const float* __restrict__ w1, const float* __restrict__ w2) {
    const int b = blockIdx.x, t = threadIdx.x;
    if (b < 16) {
        const float mnv = funmap(g_wmm[0]);
        const float sc = fmaxf((funmap(g_wmm[1]) - mnv) * (1.f / 255.f), 1e-8f);
        {
            int f = b * 256 + t;
            int m = f >> 9;
            int rem = f & 511;
            int q = rem >> 5, L = rem & 31;
            unsigned rg[4];
            #pragma unroll
            for (int r = 0; r < 4; r++) {
                int row = m * 16 + (L >> 2) + (r & 1) * 8;
                int kc = q * 32 + (r >> 1) * 16 + (L & 3) * 4;
                unsigned u = 0;
                #pragma unroll
                for (int i = 0; i < 4; i++) {
                    int code = __float2int_rn(__fdiv_rn(w1[row * C1 + kc + i] - mnv, sc));
                    u |= ((unsigned)code & 0xffu) << (8 * i);
                }
                rg[r] = u;
            }
            g_w1p[f] = make_uint4(rg[0], rg[1], rg[2], rg[3]);
        }
        {
            int wd = t >> 5, ln = t & 31;
            int co = b * 8 + wd;
            float s = 0.f;
            #pragma unroll
            for (int i = 0; i < 16; i++)
                s += (float)__float2int_rn(__fdiv_rn(w1[co * C1 + i * 32 + ln] - mnv, sc));
            s = wredsum(s);
            if (ln == 0) g_j1row[co] = s;
        }
    } else {
        __shared__ u8 s_code[C3 * C2 * 9];
        const float mnv = funmap(g_wmm[2]);
        const float sc = fmaxf((funmap(g_wmm[3]) - mnv) * (1.f / 255.f), 1e-8f);
        for (int i = t; i < C3 * C2 * 9; i += 256)
            s_code[i] = (u8)__float2int_rn(__fdiv_rn(w2[i] - mnv, sc));
        __syncthreads();
        for (int e = t; e < C3 * 9; e += 256) {
            int co = e / 9, tap = e - co * 9;
            int s = 0;
            for (int ci = 0; ci < C2; ci++) s += s_code[(co * C2 + ci) * 9 + tap];
            g_Jtap[e] = (float)s;
        }
        if (t < C3) {
            int s = 0;
            for (int i = 0; i < C2 * 9; i++) s += s_code[t * C2 * 9 + i];
            g_Jall[t] = (float)s;
        }
        for (int f = t; f < 2304; f += 256) {
            int lane = f & 31;
            int u = f >> 5;
            int mtile = u & 1;
            int v2i = u >> 1;
            int g = v2i & 3, tap = v2i >> 2;
            int co_b = mtile * 16 + (lane >> 2);
            int ci_b = g * 32 + (lane & 3) * 4;
            unsigned rg[4];
            #pragma unroll
            for (int r = 0; r < 4; r++) {
                int co = co_b + (r & 1) * 8;
                int ci0 = ci_b + (r >> 1) * 16;
                unsigned uu = 0;
                #pragma unroll
                for (int i = 0; i < 4; i++)
                    uu |= ((unsigned)s_code[(co * C2 + ci0 + i) * 9 + tap]) << (8 * i);
                rg[r] = uu;
            }
            g_w2p[f] = make_uint4(rg[0], rg[1], rg[2], rg[3]);
        }
    }
}

// ---------------- 3a: per-channel raw min/max of x (warp per plane) ----------------
__global__ __launch_bounds__(256) void h1mm_k(const float* __restrict__ x) {
    const int b = blockIdx.x, t = threadIdx.x;
    const int w = t >> 5, ln = t & 31;
    #pragma unroll
    for (int sub = 0; sub < 2; sub++) {
        const int plane = b * 16 + w * 2 + sub;      // 0..32767
        const int ci = plane & 511;
        const float4* p = (const float4*)x + plane * 196;
        float mn = FMAXV, mx = -FMAXV;
        #pragma unroll 4
        for (int i = ln; i < 196; i += 32) {
            float4 v = p[i];
            mn = fminf(mn, fminf(fminf(v.x, v.y), fminf(v.z, v.w)));
            mx = fmaxf(mx, fmaxf(fmaxf(v.x, v.y), fmaxf(v.z, v.w)));
        }
        mn = wredmin(mn); mx = wredmax(mx);
        if (ln == 0) {
            atomicMin(&g_xmn[ci], fmap(mn));
            atomicMax(&g_xmx[ci], fmap(mx));
        }
    }
}

// ---------------- 3b: fold channel extremes through relu(BN1) (monotone) ----------------
__global__ void mm2_k() {
    __shared__ float smn[16], smx[16];
    const int t = threadIdx.x, w = t >> 5, ln = t & 31;
    float a = g_a1[t], bb = g_b1v[t];
    float rmn = funmap(g_xmn[t]), rmx = funmap(g_xmx[t]);
    float lo = fmaxf(fmaf(a, (a >= 0.f) ? rmn : rmx, bb), 0.f);
    float hi = fmaxf(fmaf(a, (a >= 0.f) ? rmx : rmn, bb), 0.f);
    lo = wredmin(lo); hi = wredmax(hi);
    if (ln == 0) { smn[w] = lo; smx[w] = hi; }
    __syncthreads();
    if (w == 0) {
        float m2 = (ln < 16) ? smn[ln] : FMAXV;
        float M2 = (ln < 16) ? smx[ln] : 0.f;
        m2 = wredmin(m2); M2 = wredmax(M2);
        if (ln == 0) { g_h1mn = __float_as_uint(m2); g_h1mx = __float_as_uint(M2); }
    }
}

// ---------------- 4: conv1x1 via u8 IMMA, k32 chunks, 4 CTAs/SM ----------------
#define BP1 48
#define BUF1 (64*BP1)   // 3072 B
__global__ __launch_bounds__(256, 4) void conv1_k(const float* __restrict__ x) {
    __shared__ __align__(16) u8 Bs[2 * BUF1];
    __shared__ int kcp[4][64];
    __shared__ float kcolF[64];
    __shared__ float sa1[C1], sb1[C1];
    __shared__ float smn[8], smx[8];

    const int tid = threadIdx.x;
    const int lane = tid & 31, wid = tid >> 5;
    const int col0 = blockIdx.x * 64;

    #pragma unroll
    for (int l = 0; l < 2; l++) {
        int e = tid + l * 256;
        sa1[e] = g_a1[e]; sb1[e] = g_b1v[e];
    }

    const float mn1 = __uint_as_float(g_h1mn);
    const float mx1 = __uint_as_float(g_h1mx);
    const float s1 = fmaxf((mx1 - mn1) * (1.f / 255.f), 1e-8f);
    const float i1 = 1.f / s1;

    const int pB = tid & 63;
    const int tq = tid >> 6;        // ci-octet within chunk
    const int gpB = col0 + pB;
    const int nimgB = gpB / 784;
    const float* xb = x + nimgB * C1 * HW + (gpB - nimgB * 784) + tq * 8 * HW;

    int acc[8][4];
    #pragma unroll
    for (int t = 0; t < 8; t++)
        #pragma unroll
        for (int r = 0; r < 4; r++) acc[t][r] = 0;

    float v[8];
    int ksum = 0;
    #pragma unroll
    for (int j = 0; j < 8; j++) v[j] = xb[j * HW];
    __syncthreads();   // sa1/sb1 ready

    // produce chunk 0
    {
        const int cib = tq * 8;
        #pragma unroll
        for (int s = 0; s < 2; s++) {
            unsigned u = 0;
            #pragma unroll
            for (int j = 0; j < 4; j++) {
                int ci = cib + s * 4 + j;
                float h = fmaxf(fmaf(sa1[ci], v[s * 4 + j], sb1[ci]), 0.f);
                int code = __float2int_rn((h - mn1) * i1);
                ksum += code;
                u |= ((unsigned)code & 0xffu) << (8 * j);
            }
            *(unsigned*)(Bs + pB * BP1 + tq * 8 + s * 4) = u;
        }
    }
    // prefetch chunk 1
    #pragma unroll
    for (int j = 0; j < 8; j++) v[j] = xb[(32 + j) * HW];
    __syncthreads();

    for (int c = 0; c < 16; c++) {
        const u8* curB = Bs + (c & 1) * BUF1;
        if (c < 15) {
            u8* nxtB = Bs + ((c + 1) & 1) * BUF1;
            const int cib = (c + 1) * 32 + tq * 8;
            #pragma unroll
            for (int s = 0; s < 2; s++) {
                unsigned u = 0;
                #pragma unroll
                for (int j = 0; j < 4; j++) {
                    int ci = cib + s * 4 + j;
                    float h = fmaxf(fmaf(sa1[ci], v[s * 4 + j], sb1[ci]), 0.f);
                    int code = __float2int_rn((h - mn1) * i1);
                    ksum += code;
                    u |= ((unsigned)code & 0xffu) << (8 * j);
                }
                *(unsigned*)(nxtB + pB * BP1 + tq * 8 + s * 4) = u;
            }
            if (c < 14) {
                #pragma unroll
                for (int j = 0; j < 8; j++) v[j] = xb[((c + 2) * 32 + j) * HW];
            }
        }
        {
            uint4 a = g_w1p[(wid * 16 + c) * 32 + lane];
            const u8* bbase = curB + (lane >> 2) * BP1 + (lane & 3) * 4;
            #pragma unroll
            for (int t = 0; t < 8; t++) {
                unsigned b0 = *(const unsigned*)(bbase + t * 8 * BP1);
                unsigned b1 = *(const unsigned*)(bbase + t * 8 * BP1 + 16);
                mma_u8(acc[t], a.x, a.y, a.z, a.w, b0, b1);
            }
        }
        __syncthreads();
    }

    kcp[tq][pB] = ksum;
    __syncthreads();
    if (tid < 64) kcolF[tid] = (float)(kcp[0][tid] + kcp[1][tid] + kcp[2][tid] + kcp[3][tid]);
    __syncthreads();

    const float mnv = funmap(g_wmm[0]);
    const float sw = fmaxf((funmap(g_wmm[1]) - mnv) * (1.f / 255.f), 1e-8f);
    const float cS = sw * s1;
    const float cK = mnv * s1;
    const float cJ = sw * mn1;
    const float cD = 512.f * mnv * mn1;

    const int g = lane >> 2;
    const int co0 = wid * 16 + g, co1 = co0 + 8;
    const float base0 = fmaf(cJ, g_j1row[co0], cD);
    const float base1 = fmaf(cJ, g_j1row[co1], cD);
    const float a20 = g_a2[co0], b20 = g_b2v[co0];
    const float a21 = g_a2[co1], b21 = g_b2v[co1];

    float lmn = FMAXV, lmx = 0.f;
    #pragma unroll
    for (int t = 0; t < 8; t++) {
        int pl = t * 8 + (lane & 3) * 2;
        float kc0 = kcolF[pl], kc1 = kcolF[pl + 1];
        float y00 = fmaf(cS, __int2float_rn(acc[t][0]), fmaf(cK, kc0, base0));
        float y01 = fmaf(cS, __int2float_rn(acc[t][1]), fmaf(cK, kc1, base0));
        float y10 = fmaf(cS, __int2float_rn(acc[t][2]), fmaf(cK, kc0, base1));
        float y11 = fmaf(cS, __int2float_rn(acc[t][3]), fmaf(cK, kc1, base1));
        float h00 = fmaxf(fmaf(a20, y00, b20), 0.f);
        float h01 = fmaxf(fmaf(a20, y01, b20), 0.f);
        float h10 = fmaxf(fmaf(a21, y10, b21), 0.f);
        float h11 = fmaxf(fmaf(a21, y11, b21), 0.f);
        lmn = fminf(lmn, fminf(fminf(h00, h01), fminf(h10, h11)));
        lmx = fmaxf(lmx, fmaxf(fmaxf(h00, h01), fmaxf(h10, h11)));
        int px0 = col0 + pl;
        g_h2buf[px0 * C2 + co0]       = h00;
        g_h2buf[(px0 + 1) * C2 + co0] = h01;
        g_h2buf[px0 * C2 + co1]       = h10;
        g_h2buf[(px0 + 1) * C2 + co1] = h11;
    }
    float bm = wredmin(lmn), bM = wredmax(lmx);
    if (lane == 0) { smn[wid] = bm; smx[wid] = bM; }
    __syncthreads();
    if (wid == 0) {
        float m2 = (lane < 8) ? smn[lane] : FMAXV;
        float M2 = (lane < 8) ? smx[lane] : 0.f;
        m2 = wredmin(m2); M2 = wredmax(M2);
        if (lane == 0) {
            atomicMin(&g_h2mn, __float_as_uint(m2));
            atomicMax(&g_h2mx, __float_as_uint(M2));
        }
    }
}

// ---------------- 4.5: h2 -> u8 codes (8 threads/pixel, coalesced) ----------------
__global__ __launch_bounds__(256) void codes_k() {
    const int t = blockIdx.x * 256 + threadIdx.x;
    const int gp = t >> 3;
    const int sub = t & 7;
    const float mn = __uint_as_float(g_h2mn);
    const float mx = __uint_as_float(g_h2mx);
    const float s = fmaxf((mx - mn) * (1.f / 255.f), 1e-8f);
    const float inv = 1.f / s;
    const float4* src = (const float4*)(g_h2buf + (size_t)gp * C2) + sub * 4;
    int ksum = 0;
    unsigned wds[4];
    #pragma unroll
    for (int j = 0; j < 4; j++) {
        float4 v = src[j];
        int c0 = __float2int_rn((v.x - mn) * inv);
        int c1 = __float2int_rn((v.y - mn) * inv);
        int c2 = __float2int_rn((v.z - mn) * inv);
        int c3 = __float2int_rn((v.w - mn) * inv);
        ksum += c0 + c1 + c2 + c3;
        wds[j] = (unsigned)c0 | ((unsigned)c1 << 8) | ((unsigned)c2 << 16) | ((unsigned)c3 << 24);
    }
    ((uint4*)(g_h2q + (size_t)gp * C2))[sub] = make_uint4(wds[0], wds[1], wds[2], wds[3]);
    ksum += __shfl_down_sync(0xffffffffu, ksum, 4, 8);
    ksum += __shfl_down_sync(0xffffffffu, ksum, 2, 8);
    ksum += __shfl_down_sync(0xffffffffu, ksum, 1, 8);
    if (sub == 0) g_T[gp] = (float)ksum;
}

// ---------------- 5: conv3x3 via u8 IMMA, smem-staged zero-padded codes ----------------
#define BP2 144
__global__ __launch_bounds__(224) void conv2_k(float* __restrict__ out) {
    __shared__ uint4 s_w[2304];
    __shared__ __align__(16) u8 s_b[4 * 30 * BP2];
    __shared__ float s_T[4 * 28];
    __shared__ float s_K9[56];
    __shared__ float s_Jtap[C3 * 9];
    __shared__ float s_Jall[C3];

    const int tid = threadIdx.x;
    const int lane = tid & 31, wid = tid >> 5;
    const int n = blockIdx.y, sl = blockIdx.x;
    const int r0 = sl * 2;

    for (int f = tid; f < 2304; f += 224) s_w[f] = g_w2p[f];
    for (int idx = tid; idx < 4 * 30 * 8; idx += 224) {
        int j = idx & 7;
        int slot = idx >> 3;
        int cc = slot % 30, l = slot / 30;
        int gr = r0 - 1 + l, gc = cc - 1;
        uint4 vv = make_uint4(0u, 0u, 0u, 0u);
        if ((unsigned)gr < 28u && (unsigned)gc < 28u)
            vv = *(const uint4*)(g_h2q + ((size_t)(n * 784 + gr * 28 + gc)) * C2 + j * 16);
        *(uint4*)(s_b + (size_t)slot * BP2 + j * 16) = vv;
    }
    for (int e = tid; e < 112; e += 224) {
        int rr = r0 - 1 + e / 28, cc = e - (e / 28) * 28;
        s_T[e] = ((unsigned)rr < 28u) ? g_T[n * 784 + rr * 28 + cc] : 0.f;
    }
    for (int e = tid; e < C3 * 9; e += 224) s_Jtap[e] = g_Jtap[e];
    if (tid < C3) s_Jall[tid] = g_Jall[tid];
    __syncthreads();
    if (tid < 56) {
        int rl = tid / 28, c = tid - rl * 28;
        float s = 0.f;
        #pragma unroll
        for (int dr = 0; dr < 3; dr++) {
            #pragma unroll
            for (int dc = -1; dc <= 1; dc++) {
                int cc = c + dc;
                if ((unsigned)cc < 28u) s += s_T[(rl + dr) * 28 + cc];
            }
        }
        s_K9[tid] = s;
    }
    __syncthreads();

    const int ql = wid * 8 + (lane >> 2);
    const int rl = ql / 28, cl = ql - (ql / 28) * 28;

    int acc0[4] = {0, 0, 0, 0}, acc1[4] = {0, 0, 0, 0};

    #pragma unroll
    for (int t = 0; t < 9; t++) {
        const int dr = t / 3, dc = t % 3;
        const u8* bt = s_b + (size_t)((rl + dr) * 30 + (cl + dc)) * BP2 + (lane & 3) * 4;
        #pragma unroll
        for (int g = 0; g < 4; g++) {
            unsigned b0 = *(const unsigned*)(bt + g * 32);
            unsigned b1 = *(const unsigned*)(bt + g * 32 + 16);
            uint4 a0 = s_w[((t * 4 + g) * 2 + 0) * 32 + lane];
            mma_u8(acc0, a0.x, a0.y, a0.z, a0.w, b0, b1);
            uint4 a1 = s_w[((t * 4 + g) * 2 + 1) * 32 + lane];
            mma_u8(acc1, a1.x, a1.y, a1.z, a1.w, b0, b1);
        }
    }

    const float mn2 = __uint_as_float(g_h2mn);
    const float mx2 = __uint_as_float(g_h2mx);
    const float s2 = fmaxf((mx2 - mn2) * (1.f / 255.f), 1e-8f);
    const float mnv = funmap(g_wmm[2]);
    const float sw = fmaxf((funmap(g_wmm[3]) - mnv) * (1.f / 255.f), 1e-8f);
    const float cS = sw * s2;
    const float cK = mnv * s2;
    const float cJ = sw * mn2;
    const float cD = 1152.f * mnv * mn2;

    const int qa = wid * 8 + 2 * (lane & 3);
    const int co_r = lane >> 2;

    #pragma unroll
    for (int e = 0; e < 2; e++) {
        const int q = qa + e;
        const float k9 = s_K9[q];
        const int r = r0 + q / 28, c = q - (q / 28) * 28;
        const bool border = (r == 0) | (r == 27) | (c == 0) | (c == 27);
        int npad = 0;
        float sj[4] = {0.f, 0.f, 0.f, 0.f};
        if (border) {
            #pragma unroll
            for (int t = 0; t < 9; t++) {
                const int dr = t / 3 - 1, dc = t % 3 - 1;
                const bool pad = ((unsigned)(r + dr) >= 28u) || ((unsigned)(c + dc) >= 28u);
                if (pad) {
                    npad++;
                    #pragma unroll
                    for (int m = 0; m < 4; m++) sj[m] += s_Jtap[(co_r + 8 * m) * 9 + t];
                }
            }
        }
        #pragma unroll
        for (int m = 0; m < 4; m++) {
            const int co = co_r + 8 * m;
            int S = (m == 0) ? acc0[0 + e] : (m == 1) ? acc0[2 + e] : (m == 2) ? acc1[0 + e] : acc1[2 + e];
            float y = fmaf(cS, __int2float_rn(S), fmaf(cK, k9, fmaf(cJ, s_Jall[co], cD)));
            if (border) y -= mn2 * fmaf(sw, sj[m], mnv * 128.f * (float)npad);
            out[(n * C3 + co) * HW + r * 28 + c] = y;
        }
    }
}

// ---------------- launch ----------------
extern "C" void kernel_launch(void* const* d_in, const int* in_sizes, int n_in,
                              void* d_out, int out_size) {
    const float* x  = (const float*)d_in[0];
    const float* g1 = (const float*)d_in[1];
    const float* b1 = (const float*)d_in[2];
    const float* m1 = (const float*)d_in[3];
    const float* v1 = (const float*)d_in[4];
    const float* w1 = (const float*)d_in[5];
    const float* g2 = (const float*)d_in[6];
    const float* b2 = (const float*)d_in[7];
    const float* m2 = (const float*)d_in[8];
    const float* v2 = (const float*)d_in[9];
    const float* w2 = (const float*)d_in[10];
    float* out = (float*)d_out;

    prep_k<<<1, 512>>>(g1, b1, m1, v1, g2, b2, m2, v2);
    wmm_k<<<24, 256>>>(w1, w2);
    wpack_k<<<17, 256>>>(w1, w2);
    h1mm_k<<<2048, 256>>>(x);
    mm2_k<<<1, 512>>>();
    conv1_k<<<NPIX / 64, 256>>>(x);
    codes_k<<<NPIX * 8 / 256, 256>>>();
    conv2_k<<<dim3(14, Nn), 224>>>(out);
}

// round 15
// speedup vs baseline: 1.3005x; 1.2711x over previous
#include <cuda_runtime.h>

typedef unsigned long long ull;
typedef unsigned char u8;

#define Nn 64
#define C1 512
#define C2 128
#define C3 32
#define HW 784
#define NPIX (Nn*HW)   // 50176

#define FMAXV 3.402823466e38f

// ---------------- device scratch ----------------
__device__ float g_a1[C1], g_b1v[C1], g_a2[C2], g_b2v[C2];
__device__ uint4 g_w1p[8*16*32];                // w1 u8 codes, mma-fragment-permuted
__device__ float g_j1row[C2];                   // per-co sum of w1 codes
__device__ uint4 g_w2p[2304];                   // w2 codes fragment-packed
__device__ float g_Jtap[C3*9];                  // per-(co,tap) code sums
__device__ float g_Jall[C3];                    // per-co total code sums
__device__ __align__(16) float g_h2buf[NPIX*C2];   // h2 pre-quant, [pixel][co] layout
__device__ __align__(16) u8    g_h2q[NPIX*C2];     // h2 u8 codes, [pixel][ci] layout
__device__ float g_T[NPIX];                        // per-pixel sum of codes
__device__ unsigned g_h1mn, g_h1mx, g_h2mn, g_h2mx;  // nonneg floats as uint bits
__device__ float g_xpmn[Nn*C1], g_xpmx[Nn*C1];  // per-plane raw x min/max partials
__device__ float g_wpmn[24], g_wpmx[24];        // weight min/max partials
__device__ float g_w1mn, g_w1s, g_w2mn, g_w2s;  // final weight quant params

// ---------------- helpers ----------------
__device__ __forceinline__ void mma_u8(int* d, unsigned a0, unsigned a1, unsigned a2, unsigned a3,
                                       unsigned b0, unsigned b1) {
    asm volatile("mma.sync.aligned.m16n8k32.row.col.s32.u8.u8.s32 "
                 "{%0,%1,%2,%3},{%4,%5,%6,%7},{%8,%9},{%0,%1,%2,%3};"
                 : "+r"(d[0]), "+r"(d[1]), "+r"(d[2]), "+r"(d[3])
                 : "r"(a0), "r"(a1), "r"(a2), "r"(a3), "r"(b0), "r"(b1));
}
__device__ __forceinline__ float wredmin(float v) {
    #pragma unroll
    for (int o = 16; o > 0; o >>= 1) v = fminf(v, __shfl_xor_sync(0xffffffffu, v, o));
    return v;
}
__device__ __forceinline__ float wredmax(float v) {
    #pragma unroll
    for (int o = 16; o > 0; o >>= 1) v = fmaxf(v, __shfl_xor_sync(0xffffffffu, v, o));
    return v;
}
__device__ __forceinline__ float wredsum(float v) {
    #pragma unroll
    for (int o = 16; o > 0; o >>= 1) v += __shfl_xor_sync(0xffffffffu, v, o);
    return v;
}

// ---------------- 1: pass1 — h1 plane partials + weight min/max partials ----------------
// blocks 0..2047: x plane min/max (16 planes each, warp per 2 planes)
// blocks 2048..2063: w1 chunks; 2064..2071: w2 chunks
__global__ __launch_bounds__(256) void pass1_k(const float* __restrict__ x,
                                               const float* __restrict__ w1,
                                               const float* __restrict__ w2) {
    const int b = blockIdx.x, t = threadIdx.x;
    const int w = t >> 5, ln = t & 31;
    if (b < 2048) {
        #pragma unroll
        for (int sub = 0; sub < 2; sub++) {
            const int plane = b * 16 + w * 2 + sub;      // = img*512 + ci
            const float4* p = (const float4*)x + plane * 196;
            float mn = FMAXV, mx = -FMAXV;
            #pragma unroll 4
            for (int i = ln; i < 196; i += 32) {
                float4 v = p[i];
                mn = fminf(mn, fminf(fminf(v.x, v.y), fminf(v.z, v.w)));
                mx = fmaxf(mx, fmaxf(fmaxf(v.x, v.y), fmaxf(v.z, v.w)));
            }
            mn = wredmin(mn); mx = wredmax(mx);
            if (ln == 0) { g_xpmn[plane] = mn; g_xpmx[plane] = mx; }
        }
    } else {
        __shared__ float smn[8], smx[8];
        const int b2 = b - 2048;
        const float* wp; int cnt;
        if (b2 < 16) { wp = w1 + b2 * 4096; cnt = 4096; }
        else         { wp = w2 + (b2 - 16) * 4608; cnt = 4608; }
        float mn = FMAXV, mx = -FMAXV;
        for (int i = t; i < cnt; i += 256) { float v = wp[i]; mn = fminf(mn, v); mx = fmaxf(mx, v); }
        float bm = wredmin(mn), bM = wredmax(mx);
        if (ln == 0) { smn[w] = bm; smx[w] = bM; }
        __syncthreads();
        if (w == 0) {
            float m2 = (ln < 8) ? smn[ln] : FMAXV;
            float M2 = (ln < 8) ? smx[ln] : -FMAXV;
            m2 = wredmin(m2); M2 = wredmax(M2);
            if (ln == 0) { g_wpmn[b2] = m2; g_wpmx[b2] = M2; }
        }
    }
}

// ---------------- 2: pack — weight pack + BN affines + h1 range fold ----------------
// blocks 0..15: w1 fragment pack + j1row; block 16: w2 pack + Jtap/Jall; block 17: prep + mm2
__global__ __launch_bounds__(256) void pack_k(const float* __restrict__ w1,
                                              const float* __restrict__ w2,
                                              const float* __restrict__ g1, const float* __restrict__ b1,
                                              const float* __restrict__ m1, const float* __restrict__ v1,
                                              const float* __restrict__ g2, const float* __restrict__ b2,
                                              const float* __restrict__ m2, const float* __restrict__ v2) {
    const int b = blockIdx.x, t = threadIdx.x;
    if (b < 16) {
        float mnv = FMAXV, mxv = -FMAXV;
        #pragma unroll
        for (int i = 0; i < 16; i++) { mnv = fminf(mnv, g_wpmn[i]); mxv = fmaxf(mxv, g_wpmx[i]); }
        const float sc = fmaxf((mxv - mnv) * (1.f / 255.f), 1e-8f);
        if (b == 0 && t == 0) { g_w1mn = mnv; g_w1s = sc; }
        {
            int f = b * 256 + t;
            int m = f >> 9;
            int rem = f & 511;
            int q = rem >> 5, L = rem & 31;
            unsigned rg[4];
            #pragma unroll
            for (int r = 0; r < 4; r++) {
                int row = m * 16 + (L >> 2) + (r & 1) * 8;
                int kc = q * 32 + (r >> 1) * 16 + (L & 3) * 4;
                unsigned u = 0;
                #pragma unroll
                for (int i = 0; i < 4; i++) {
                    int code = __float2int_rn(__fdiv_rn(w1[row * C1 + kc + i] - mnv, sc));
                    u |= ((unsigned)code & 0xffu) << (8 * i);
                }
                rg[r] = u;
            }
            g_w1p[f] = make_uint4(rg[0], rg[1], rg[2], rg[3]);
        }
        {
            int wd = t >> 5, ln = t & 31;
            int co = b * 8 + wd;
            float s = 0.f;
            #pragma unroll
            for (int i = 0; i < 16; i++)
                s += (float)__float2int_rn(__fdiv_rn(w1[co * C1 + i * 32 + ln] - mnv, sc));
            s = wredsum(s);
            if (ln == 0) g_j1row[co] = s;
        }
    } else if (b == 16) {
        __shared__ u8 s_code[C3 * C2 * 9];
        __shared__ float s_jt[C3 * 9];
        float mnv = FMAXV, mxv = -FMAXV;
        #pragma unroll
        for (int i = 16; i < 24; i++) { mnv = fminf(mnv, g_wpmn[i]); mxv = fmaxf(mxv, g_wpmx[i]); }
        const float sc = fmaxf((mxv - mnv) * (1.f / 255.f), 1e-8f);
        if (t == 0) { g_w2mn = mnv; g_w2s = sc; }
        for (int i = t; i < C3 * C2 * 9; i += 256)
            s_code[i] = (u8)__float2int_rn(__fdiv_rn(w2[i] - mnv, sc));
        __syncthreads();
        for (int e = t; e < C3 * 9; e += 256) {
            int co = e / 9, tap = e - co * 9;
            int s = 0;
            for (int ci = 0; ci < C2; ci++) s += s_code[(co * C2 + ci) * 9 + tap];
            g_Jtap[e] = (float)s;
            s_jt[e] = (float)s;
        }
        __syncthreads();
        if (t < C3) {
            float s = 0.f;
            #pragma unroll
            for (int k = 0; k < 9; k++) s += s_jt[t * 9 + k];
            g_Jall[t] = s;
        }
        for (int f = t; f < 2304; f += 256) {
            int lane = f & 31;
            int u = f >> 5;
            int mtile = u & 1;
            int v2i = u >> 1;
            int g = v2i & 3, tap = v2i >> 2;
            int co_b = mtile * 16 + (lane >> 2);
            int ci_b = g * 32 + (lane & 3) * 4;
            unsigned rg[4];
            #pragma unroll
            for (int r = 0; r < 4; r++) {
                int co = co_b + (r & 1) * 8;
                int ci0 = ci_b + (r >> 1) * 16;
                unsigned uu = 0;
                #pragma unroll
                for (int i = 0; i < 4; i++)
                    uu |= ((unsigned)s_code[(co * C2 + ci0 + i) * 9 + tap]) << (8 * i);
                rg[r] = uu;
            }
            g_w2p[f] = make_uint4(rg[0], rg[1], rg[2], rg[3]);
        }
    } else {
        // block 17: BN affines + fold x partials through relu(BN1) + reset h2 range
        __shared__ float smn[8], smx[8];
        const int w = t >> 5, ln = t & 31;
        float lo = FMAXV, hi = 0.f;
        #pragma unroll
        for (int l = 0; l < 2; l++) {
            int ci = t + 256 * l;
            float inv = g1[ci] / sqrtf(v1[ci] + 1e-5f);
            float bb = b1[ci] - m1[ci] * inv;
            g_a1[ci] = inv; g_b1v[ci] = bb;
            float rmn = FMAXV, rmx = -FMAXV;
            #pragma unroll 4
            for (int img = 0; img < Nn; img++) {
                rmn = fminf(rmn, g_xpmn[img * C1 + ci]);
                rmx = fmaxf(rmx, g_xpmx[img * C1 + ci]);
            }
            float l0 = fmaxf(fmaf(inv, (inv >= 0.f) ? rmn : rmx, bb), 0.f);
            float h0 = fmaxf(fmaf(inv, (inv >= 0.f) ? rmx : rmn, bb), 0.f);
            lo = fminf(lo, l0); hi = fmaxf(hi, h0);
        }
        if (t < C2) {
            float inv2 = g2[t] / sqrtf(v2[t] + 1e-5f);
            g_a2[t] = inv2; g_b2v[t] = b2[t] - m2[t] * inv2;
        }
        lo = wredmin(lo); hi = wredmax(hi);
        if (ln == 0) { smn[w] = lo; smx[w] = hi; }
        __syncthreads();
        if (w == 0) {
            float m2v = (ln < 8) ? smn[ln] : FMAXV;
            float M2v = (ln < 8) ? smx[ln] : 0.f;
            m2v = wredmin(m2v); M2v = wredmax(M2v);
            if (ln == 0) {
                g_h1mn = __float_as_uint(m2v);
                g_h1mx = __float_as_uint(M2v);
                g_h2mn = 0x7f7fffffu;
                g_h2mx = 0u;
            }
        }
    }
}

// ---------------- 3: conv1x1 via u8 IMMA, k32 chunks, 4 CTAs/SM ----------------
#define BP1 48
#define BUF1 (64*BP1)   // 3072 B
__global__ __launch_bounds__(256, 4) void conv1_k(const float* __restrict__ x) {
    __shared__ __align__(16) u8 Bs[2 * BUF1];
    __shared__ int kcp[4][64];
    __shared__ float kcolF[64];
    __shared__ float sa1[C1], sb1[C1];
    __shared__ float smn[8], smx[8];

    const int tid = threadIdx.x;
    const int lane = tid & 31, wid = tid >> 5;
    const int col0 = blockIdx.x * 64;

    #pragma unroll
    for (int l = 0; l < 2; l++) {
        int e = tid + l * 256;
        sa1[e] = g_a1[e]; sb1[e] = g_b1v[e];
    }

    const float mn1 = __uint_as_float(g_h1mn);
    const float mx1 = __uint_as_float(g_h1mx);
    const float s1 = fmaxf((mx1 - mn1) * (1.f / 255.f), 1e-8f);
    const float i1 = 1.f / s1;

    const int pB = tid & 63;
    const int tq = tid >> 6;        // ci-octet within chunk
    const int gpB = col0 + pB;
    const int nimgB = gpB / 784;
    const float* xb = x + nimgB * C1 * HW + (gpB - nimgB * 784) + tq * 8 * HW;

    int acc[8][4];
    #pragma unroll
    for (int t = 0; t < 8; t++)
        #pragma unroll
        for (int r = 0; r < 4; r++) acc[t][r] = 0;

    float v[8];
    int ksum = 0;
    #pragma unroll
    for (int j = 0; j < 8; j++) v[j] = xb[j * HW];
    __syncthreads();   // sa1/sb1 ready

    // produce chunk 0
    {
        const int cib = tq * 8;
        #pragma unroll
        for (int s = 0; s < 2; s++) {
            unsigned u = 0;
            #pragma unroll
            for (int j = 0; j < 4; j++) {
                int ci = cib + s * 4 + j;
                float h = fmaxf(fmaf(sa1[ci], v[s * 4 + j], sb1[ci]), 0.f);
                int code = __float2int_rn((h - mn1) * i1);
                ksum += code;
                u |= ((unsigned)code & 0xffu) << (8 * j);
            }
            *(unsigned*)(Bs + pB * BP1 + tq * 8 + s * 4) = u;
        }
    }
    // prefetch chunk 1
    #pragma unroll
    for (int j = 0; j < 8; j++) v[j] = xb[(32 + j) * HW];
    __syncthreads();

    for (int c = 0; c < 16; c++) {
        const u8* curB = Bs + (c & 1) * BUF1;
        if (c < 15) {
            u8* nxtB = Bs + ((c + 1) & 1) * BUF1;
            const int cib = (c + 1) * 32 + tq * 8;
            #pragma unroll
            for (int s = 0; s < 2; s++) {
                unsigned u = 0;
                #pragma unroll
                for (int j = 0; j < 4; j++) {
                    int ci = cib + s * 4 + j;
                    float h = fmaxf(fmaf(sa1[ci], v[s * 4 + j], sb1[ci]), 0.f);
                    int code = __float2int_rn((h - mn1) * i1);
                    ksum += code;
                    u |= ((unsigned)code & 0xffu) << (8 * j);
                }
                *(unsigned*)(nxtB + pB * BP1 + tq * 8 + s * 4) = u;
            }
            if (c < 14) {
                #pragma unroll
                for (int j = 0; j < 8; j++) v[j] = xb[((c + 2) * 32 + j) * HW];
            }
        }
        {
            uint4 a = g_w1p[(wid * 16 + c) * 32 + lane];
            const u8* bbase = curB + (lane >> 2) * BP1 + (lane & 3) * 4;
            #pragma unroll
            for (int t = 0; t < 8; t++) {
                unsigned b0 = *(const unsigned*)(bbase + t * 8 * BP1);
                unsigned b1 = *(const unsigned*)(bbase + t * 8 * BP1 + 16);
                mma_u8(acc[t], a.x, a.y, a.z, a.w, b0, b1);
            }
        }
        __syncthreads();
    }

    kcp[tq][pB] = ksum;
    __syncthreads();
    if (tid < 64) kcolF[tid] = (float)(kcp[0][tid] + kcp[1][tid] + kcp[2][tid] + kcp[3][tid]);
    __syncthreads();

    const float mnv = g_w1mn;
    const float sw = g_w1s;
    const float cS = sw * s1;
    const float cK = mnv * s1;
    const float cJ = sw * mn1;
    const float cD = 512.f * mnv * mn1;

    const int g = lane >> 2;
    const int co0 = wid * 16 + g, co1 = co0 + 8;
    const float base0 = fmaf(cJ, g_j1row[co0], cD);
    const float base1 = fmaf(cJ, g_j1row[co1], cD);
    const float a20 = g_a2[co0], b20 = g_b2v[co0];
    const float a21 = g_a2[co1], b21 = g_b2v[co1];

    float lmn = FMAXV, lmx = 0.f;
    #pragma unroll
    for (int t = 0; t < 8; t++) {
        int pl = t * 8 + (lane & 3) * 2;
        float kc0 = kcolF[pl], kc1 = kcolF[pl + 1];
        float y00 = fmaf(cS, __int2float_rn(acc[t][0]), fmaf(cK, kc0, base0));
        float y01 = fmaf(cS, __int2float_rn(acc[t][1]), fmaf(cK, kc1, base0));
        float y10 = fmaf(cS, __int2float_rn(acc[t][2]), fmaf(cK, kc0, base1));
        float y11 = fmaf(cS, __int2float_rn(acc[t][3]), fmaf(cK, kc1, base1));
        float h00 = fmaxf(fmaf(a20, y00, b20), 0.f);
        float h01 = fmaxf(fmaf(a20, y01, b20), 0.f);
        float h10 = fmaxf(fmaf(a21, y10, b21), 0.f);
        float h11 = fmaxf(fmaf(a21, y11, b21), 0.f);
        lmn = fminf(lmn, fminf(fminf(h00, h01), fminf(h10, h11)));
        lmx = fmaxf(lmx, fmaxf(fmaxf(h00, h01), fmaxf(h10, h11)));
        int px0 = col0 + pl;
        g_h2buf[px0 * C2 + co0]       = h00;
        g_h2buf[(px0 + 1) * C2 + co0] = h01;
        g_h2buf[px0 * C2 + co1]       = h10;
        g_h2buf[(px0 + 1) * C2 + co1] = h11;
    }
    float bm = wredmin(lmn), bM = wredmax(lmx);
    if (lane == 0) { smn[wid] = bm; smx[wid] = bM; }
    __syncthreads();
    if (wid == 0) {
        float m2 = (lane < 8) ? smn[lane] : FMAXV;
        float M2 = (lane < 8) ? smx[lane] : 0.f;
        m2 = wredmin(m2); M2 = wredmax(M2);
        if (lane == 0) {
            atomicMin(&g_h2mn, __float_as_uint(m2));
            atomicMax(&g_h2mx, __float_as_uint(M2));
        }
    }
}

// ---------------- 4: h2 -> u8 codes (8 threads/pixel, coalesced) ----------------
__global__ __launch_bounds__(256) void codes_k() {
    const int t = blockIdx.x * 256 + threadIdx.x;
    const int gp = t >> 3;
    const int sub = t & 7;
    const float mn = __uint_as_float(g_h2mn);
    const float mx = __uint_as_float(g_h2mx);
    const float s = fmaxf((mx - mn) * (1.f / 255.f), 1e-8f);
    const float inv = 1.f / s;
    const float4* src = (const float4*)(g_h2buf + (size_t)gp * C2) + sub * 4;
    int ksum = 0;
    unsigned wds[4];
    #pragma unroll
    for (int j = 0; j < 4; j++) {
        float4 v = src[j];
        int c0 = __float2int_rn((v.x - mn) * inv);
        int c1 = __float2int_rn((v.y - mn) * inv);
        int c2 = __float2int_rn((v.z - mn) * inv);
        int c3 = __float2int_rn((v.w - mn) * inv);
        ksum += c0 + c1 + c2 + c3;
        wds[j] = (unsigned)c0 | ((unsigned)c1 << 8) | ((unsigned)c2 << 16) | ((unsigned)c3 << 24);
    }
    ((uint4*)(g_h2q + (size_t)gp * C2))[sub] = make_uint4(wds[0], wds[1], wds[2], wds[3]);
    ksum += __shfl_down_sync(0xffffffffu, ksum, 4, 8);
    ksum += __shfl_down_sync(0xffffffffu, ksum, 2, 8);
    ksum += __shfl_down_sync(0xffffffffu, ksum, 1, 8);
    if (sub == 0) g_T[gp] = (float)ksum;
}

// ---------------- 5: conv3x3 via u8 IMMA, smem-staged zero-padded codes ----------------
#define BP2 144
__global__ __launch_bounds__(224) void conv2_k(float* __restrict__ out) {
    __shared__ uint4 s_w[2304];
    __shared__ __align__(16) u8 s_b[4 * 30 * BP2];
    __shared__ float s_T[4 * 28];
    __shared__ float s_K9[56];
    __shared__ float s_Jtap[C3 * 9];
    __shared__ float s_Jall[C3];

    const int tid = threadIdx.x;
    const int lane = tid & 31, wid = tid >> 5;
    const int n = blockIdx.y, sl = blockIdx.x;
    const int r0 = sl * 2;

    for (int f = tid; f < 2304; f += 224) s_w[f] = g_w2p[f];
    for (int idx = tid; idx < 4 * 30 * 8; idx += 224) {
        int j = idx & 7;
        int slot = idx >> 3;
        int cc = slot % 30, l = slot / 30;
        int gr = r0 - 1 + l, gc = cc - 1;
        uint4 vv = make_uint4(0u, 0u, 0u, 0u);
        if ((unsigned)gr < 28u && (unsigned)gc < 28u)
            vv = *(const uint4*)(g_h2q + ((size_t)(n * 784 + gr * 28 + gc)) * C2 + j * 16);
        *(uint4*)(s_b + (size_t)slot * BP2 + j * 16) = vv;
    }
    for (int e = tid; e < 112; e += 224) {
        int rr = r0 - 1 + e / 28, cc = e - (e / 28) * 28;
        s_T[e] = ((unsigned)rr < 28u) ? g_T[n * 784 + rr * 28 + cc] : 0.f;
    }
    for (int e = tid; e < C3 * 9; e += 224) s_Jtap[e] = g_Jtap[e];
    if (tid < C3) s_Jall[tid] = g_Jall[tid];
    __syncthreads();
    if (tid < 56) {
        int rl = tid / 28, c = tid - rl * 28;
        float s = 0.f;
        #pragma unroll
        for (int dr = 0; dr < 3; dr++) {
            #pragma unroll
            for (int dc = -1; dc <= 1; dc++) {
                int cc = c + dc;
                if ((unsigned)cc < 28u) s += s_T[(rl + dr) * 28 + cc];
            }
        }
        s_K9[tid] = s;
    }
    __syncthreads();

    const int ql = wid * 8 + (lane >> 2);
    const int rl = ql / 28, cl = ql - (ql / 28) * 28;

    int acc0[4] = {0, 0, 0, 0}, acc1[4] = {0, 0, 0, 0};

    #pragma unroll
    for (int t = 0; t < 9; t++) {
        const int dr = t / 3, dc = t % 3;
        const u8* bt = s_b + (size_t)((rl + dr) * 30 + (cl + dc)) * BP2 + (lane & 3) * 4;
        #pragma unroll
        for (int g = 0; g < 4; g++) {
            unsigned b0 = *(const unsigned*)(bt + g * 32);
            unsigned b1 = *(const unsigned*)(bt + g * 32 + 16);
            uint4 a0 = s_w[((t * 4 + g) * 2 + 0) * 32 + lane];
            mma_u8(acc0, a0.x, a0.y, a0.z, a0.w, b0, b1);
            uint4 a1 = s_w[((t * 4 + g) * 2 + 1) * 32 + lane];
            mma_u8(acc1, a1.x, a1.y, a1.z, a1.w, b0, b1);
        }
    }

    const float mn2 = __uint_as_float(g_h2mn);
    const float mx2 = __uint_as_float(g_h2mx);
    const float s2 = fmaxf((mx2 - mn2) * (1.f / 255.f), 1e-8f);
    const float mnv = g_w2mn;
    const float sw = g_w2s;
    const float cS = sw * s2;
    const float cK = mnv * s2;
    const float cJ = sw * mn2;
    const float cD = 1152.f * mnv * mn2;

    const int qa = wid * 8 + 2 * (lane & 3);
    const int co_r = lane >> 2;

    #pragma unroll
    for (int e = 0; e < 2; e++) {
        const int q = qa + e;
        const float k9 = s_K9[q];
        const int r = r0 + q / 28, c = q - (q / 28) * 28;
        const bool border = (r == 0) | (r == 27) | (c == 0) | (c == 27);
        int npad = 0;
        float sj[4] = {0.f, 0.f, 0.f, 0.f};
        if (border) {
            #pragma unroll
            for (int t = 0; t < 9; t++) {
                const int dr = t / 3 - 1, dc = t % 3 - 1;
                const bool pad = ((unsigned)(r + dr) >= 28u) || ((unsigned)(c + dc) >= 28u);
                if (pad) {
                    npad++;
                    #pragma unroll
                    for (int m = 0; m < 4; m++) sj[m] += s_Jtap[(co_r + 8 * m) * 9 + t];
                }
            }
        }
        #pragma unroll
        for (int m = 0; m < 4; m++) {
            const int co = co_r + 8 * m;
            int S = (m == 0) ? acc0[0 + e] : (m == 1) ? acc0[2 + e] : (m == 2) ? acc1[0 + e] : acc1[2 + e];
            float y = fmaf(cS, __int2float_rn(S), fmaf(cK, k9, fmaf(cJ, s_Jall[co], cD)));
            if (border) y -= mn2 * fmaf(sw, sj[m], mnv * 128.f * (float)npad);
            out[(n * C3 + co) * HW + r * 28 + c] = y;
        }
    }
}

// ---------------- launch ----------------
extern "C" void kernel_launch(void* const* d_in, const int* in_sizes, int n_in,
                              void* d_out, int out_size) {
    const float* x  = (const float*)d_in[0];
    const float* g1 = (const float*)d_in[1];
    const float* b1 = (const float*)d_in[2];
    const float* m1 = (const float*)d_in[3];
    const float* v1 = (const float*)d_in[4];
    const float* w1 = (const float*)d_in[5];
    const float* g2 = (const float*)d_in[6];
    const float* b2 = (const float*)d_in[7];
    const float* m2 = (const float*)d_in[8];
    const float* v2 = (const float*)d_in[9];
    const float* w2 = (const float*)d_in[10];
    float* out = (float*)d_out;

    pass1_k<<<2072, 256>>>(x, w1, w2);
    pack_k<<<18, 256>>>(w1, w2, g1, b1, m1, v1, g2, b2, m2, v2);
    conv1_k<<<NPIX / 64, 256>>>(x);
    codes_k<<<NPIX * 8 / 256, 256>>>();
    conv2_k<<<dim3(14, Nn), 224>>>(out);
}